// round 3
// baseline (speedup 1.0000x reference)
#include <cuda_runtime.h>
#include <cuda_bf16.h>

// Problem constants (from reference)
#define N_DET   20000
#define IN_DIM  151
#define HID_DIM 256
#define OUT_DIM 128

// Scratch: __device__ globals (allocation is forbidden). 16B-aligned for
// float4 access.
__device__ __align__(16) float g_Hs[N_DET * HID_DIM];   // relu(X @ Ws_w1 + b1)
__device__ __align__(16) float g_Ho[N_DET * HID_DIM];   // relu(X @ Wo_w1 + b1)
__device__ __align__(16) float g_S [N_DET * OUT_DIM];   // subject table
__device__ __align__(16) float g_O [N_DET * OUT_DIM];   // object table
__device__ int g_idx64;                                  // 1 if edge_inds is int64

// ---------------------------------------------------------------------------
// Probe: decide whether the edge index buffer is int64 or int32.
// Genuine int64 indices are all < 20000; misread int32 pairs have the next
// element in the high 32 bits and blow past 2^32 almost surely over 48 samples.
// Deterministic: depends only on input data.
// ---------------------------------------------------------------------------
__global__ void probe_dtype(const long long* __restrict__ e)
{
    bool ok64 = true;
    for (int i = 0; i < 48; i++) {
        long long v = e[i];
        if (v < 0 || v >= N_DET) ok64 = false;
    }
    g_idx64 = ok64 ? 1 : 0;
}

// ---------------------------------------------------------------------------
// SIMT fp32 GEMM tile: C[M,N] = A[M,K] @ B[K,N] + bias, optional ReLU.
// BM=BN=128, BK=8, 256 threads, 8x8 micro-tile per thread.
// ---------------------------------------------------------------------------
template <bool RELU>
__device__ __forceinline__ void gemm_tile(const float* __restrict__ A,
                                          const float* __restrict__ B,
                                          const float* __restrict__ bias,
                                          float* __restrict__ C,
                                          int M, int N, int K)
{
    constexpr int BM = 128, BN = 128, BK = 8, TM = 8, TN = 8;
    __shared__ __align__(16) float As[BK][BM];
    __shared__ __align__(16) float Bs[BK][BN];

    const int tid = threadIdx.x;           // 0..255
    const int tx  = tid & 15;              // 16 x 16 thread grid
    const int ty  = tid >> 4;
    const int row0 = blockIdx.y * BM;
    const int col0 = blockIdx.x * BN;

    float acc[TM][TN];
#pragma unroll
    for (int i = 0; i < TM; i++)
#pragma unroll
        for (int j = 0; j < TN; j++) acc[i][j] = 0.f;

    for (int k0 = 0; k0 < K; k0 += BK) {
        // Load A tile (BMxBK = 1024 elems): idx -> k = idx&7, m = idx>>3
#pragma unroll
        for (int i = 0; i < 4; i++) {
            int idx = tid + i * 256;
            int k = idx & 7, m = idx >> 3;
            int gr = row0 + m, gk = k0 + k;
            As[k][m] = (gr < M && gk < K) ? A[(long long)gr * K + gk] : 0.f;
        }
        // Load B tile (BKxBN = 1024 elems): idx -> k = idx>>7, n = idx&127 (coalesced)
#pragma unroll
        for (int i = 0; i < 4; i++) {
            int idx = tid + i * 256;
            int k = idx >> 7, n = idx & 127;
            int gk = k0 + k, gn = col0 + n;
            Bs[k][n] = (gk < K) ? B[(long long)gk * N + gn] : 0.f;
        }
        __syncthreads();

#pragma unroll
        for (int kk = 0; kk < BK; kk++) {
            float4 a0 = *reinterpret_cast<const float4*>(&As[kk][ty * TM]);
            float4 a1 = *reinterpret_cast<const float4*>(&As[kk][ty * TM + 4]);
            float4 b0 = *reinterpret_cast<const float4*>(&Bs[kk][tx * TN]);
            float4 b1 = *reinterpret_cast<const float4*>(&Bs[kk][tx * TN + 4]);
            float a[TM] = {a0.x, a0.y, a0.z, a0.w, a1.x, a1.y, a1.z, a1.w};
            float b[TN] = {b0.x, b0.y, b0.z, b0.w, b1.x, b1.y, b1.z, b1.w};
#pragma unroll
            for (int i = 0; i < TM; i++)
#pragma unroll
                for (int j = 0; j < TN; j++)
                    acc[i][j] = fmaf(a[i], b[j], acc[i][j]);
        }
        __syncthreads();
    }

#pragma unroll
    for (int i = 0; i < TM; i++) {
        int gr = row0 + ty * TM + i;
        if (gr >= M) continue;
#pragma unroll
        for (int j = 0; j < TN; j++) {
            int gn = col0 + tx * TN + j;
            float v = acc[i][j] + bias[gn];
            if (RELU) v = fmaxf(v, 0.f);
            C[(long long)gr * N + gn] = v;
        }
    }
}

// Stage 1: H = relu(X @ W1 + b1) for both subject (z=0) and object (z=1)
__global__ void __launch_bounds__(256, 2)
mlp_stage1(const float* __restrict__ X,
           const float* __restrict__ Ws_w1, const float* __restrict__ Ws_b1,
           const float* __restrict__ Wo_w1, const float* __restrict__ Wo_b1)
{
    const float* B    = (blockIdx.z == 0) ? Ws_w1 : Wo_w1;
    const float* bias = (blockIdx.z == 0) ? Ws_b1 : Wo_b1;
    float*       C    = (blockIdx.z == 0) ? g_Hs  : g_Ho;
    gemm_tile<true>(X, B, bias, C, N_DET, HID_DIM, IN_DIM);
}

// Stage 2: T = H @ W2 + b2 -> subject/object tables
__global__ void __launch_bounds__(256, 2)
mlp_stage2(const float* __restrict__ Ws_w2, const float* __restrict__ Ws_b2,
           const float* __restrict__ Wo_w2, const float* __restrict__ Wo_b2)
{
    const float* A    = (blockIdx.z == 0) ? g_Hs  : g_Ho;
    const float* B    = (blockIdx.z == 0) ? Ws_w2 : Wo_w2;
    const float* bias = (blockIdx.z == 0) ? Ws_b2 : Wo_b2;
    float*       C    = (blockIdx.z == 0) ? g_S   : g_O;
    gemm_tile<false>(A, B, bias, C, N_DET, OUT_DIM, HID_DIM);
}

// Edge phase: warp per edge. Gather 2x128 floats (float4 per lane), dot,
// warp shfl reduce, sigmoid. Index dtype resolved at runtime via g_idx64.
__global__ void __launch_bounds__(256)
edge_kernel(const void* __restrict__ einds, float* __restrict__ out, int nE)
{
    int w    = (blockIdx.x * blockDim.x + threadIdx.x) >> 5;
    int lane = threadIdx.x & 31;
    if (w >= nE) return;

    long long i1, i2;
    if (g_idx64) {
        const long long* e = (const long long*)einds;
        i1 = __ldg(&e[3LL * w + 1]);
        i2 = __ldg(&e[3LL * w + 2]);
    } else {
        const int* e = (const int*)einds;
        i1 = __ldg(&e[3 * w + 1]);
        i2 = __ldg(&e[3 * w + 2]);
    }

    const float4* s = reinterpret_cast<const float4*>(g_S + i1 * OUT_DIM);
    const float4* o = reinterpret_cast<const float4*>(g_O + i2 * OUT_DIM);
    float4 a = s[lane];
    float4 b = o[lane];
    float sum = a.x * b.x + a.y * b.y + a.z * b.z + a.w * b.w;

#pragma unroll
    for (int off = 16; off; off >>= 1)
        sum += __shfl_xor_sync(0xffffffffu, sum, off);

    if (lane == 0)
        out[w] = 1.f / (1.f + __expf(-sum));
}

extern "C" void kernel_launch(void* const* d_in, const int* in_sizes, int n_in,
                              void* d_out, int out_size)
{
    const float* X     = (const float*)d_in[0];
    const void*  E     = d_in[1];
    const float* Ws_w1 = (const float*)d_in[2];
    const float* Ws_b1 = (const float*)d_in[3];
    const float* Ws_w2 = (const float*)d_in[4];
    const float* Ws_b2 = (const float*)d_in[5];
    const float* Wo_w1 = (const float*)d_in[6];
    const float* Wo_b1 = (const float*)d_in[7];
    const float* Wo_w2 = (const float*)d_in[8];
    const float* Wo_b2 = (const float*)d_in[9];

    probe_dtype<<<1, 1>>>((const long long*)E);

    const int mtiles = (N_DET + 127) / 128;          // 157

    dim3 g1(HID_DIM / 128, mtiles, 2);               // (2, 157, 2)
    mlp_stage1<<<g1, 256>>>(X, Ws_w1, Ws_b1, Wo_w1, Wo_b1);

    dim3 g2(OUT_DIM / 128, mtiles, 2);               // (1, 157, 2)
    mlp_stage2<<<g2, 256>>>(Ws_w2, Ws_b2, Wo_w2, Wo_b2);

    int nE = in_sizes[1] / 3;                        // 1,000,000
    int nThreads = 256;
    long long totalThreads = (long long)nE * 32;
    int nBlocks = (int)((totalThreads + nThreads - 1) / nThreads);
    edge_kernel<<<nBlocks, nThreads>>>(E, (float*)d_out, nE);
}

// round 5
// speedup vs baseline: 1.3930x; 1.3930x over previous
#include <cuda_runtime.h>
#include <cuda_bf16.h>

// Problem constants (from reference)
#define N_DET   20000
#define IN_DIM  151
#define HID_DIM 256
#define OUT_DIM 128

// Scratch: __device__ globals (allocation is forbidden). 16B-aligned.
__device__ __align__(16) float g_Hs[N_DET * HID_DIM];   // relu(X @ Ws_w1 + b1)
__device__ __align__(16) float g_Ho[N_DET * HID_DIM];   // relu(X @ Wo_w1 + b1)
__device__ __align__(16) float g_S [N_DET * OUT_DIM];   // subject table
__device__ __align__(16) float g_O [N_DET * OUT_DIM];   // object table
__device__ int g_idx64;                                  // 1 if edge_inds is int64

// ---------------------------------------------------------------------------
// Probe: decide whether the edge index buffer is int64 or int32.
// ---------------------------------------------------------------------------
__global__ void probe_dtype(const long long* __restrict__ e)
{
    bool ok64 = true;
    for (int i = 0; i < 48; i++) {
        long long v = e[i];
        if (v < 0 || v >= N_DET) ok64 = false;
    }
    g_idx64 = ok64 ? 1 : 0;
}

// ---------------------------------------------------------------------------
// tf32 helpers
// ---------------------------------------------------------------------------
__device__ __forceinline__ unsigned f2tf32(float x)
{
    unsigned r;
    asm("cvt.rna.tf32.f32 %0, %1;" : "=r"(r) : "f"(x));
    return r;
}

// D += A(16x8,row) * B(8x8,col); tf32 inputs, fp32 accum.
__device__ __forceinline__ void mma_tf32(float* d, const unsigned* a, const unsigned* b)
{
    asm("mma.sync.aligned.m16n8k8.row.col.f32.tf32.tf32.f32 "
        "{%0,%1,%2,%3}, {%4,%5,%6,%7}, {%8,%9}, {%0,%1,%2,%3};"
        : "+f"(d[0]), "+f"(d[1]), "+f"(d[2]), "+f"(d[3])
        : "r"(a[0]), "r"(a[1]), "r"(a[2]), "r"(a[3]), "r"(b[0]), "r"(b[1]));
}

// ---------------------------------------------------------------------------
// 3xTF32 GEMM tile: C[M,N] = A[M,K] @ B[K,N] + bias, optional ReLU.
// BM=128, BN=128, BK=16, 256 threads (8 warps as 2x4), warp tile 64x32.
// Near-fp32 accuracy: x = hi + lo, product = hi*hi + hi*lo + lo*hi.
// ---------------------------------------------------------------------------
template <bool RELU>
__device__ __forceinline__ void gemm_tf32_tile(const float* __restrict__ A,
                                               const float* __restrict__ B,
                                               const float* __restrict__ bias,
                                               float* __restrict__ C,
                                               int M, int N, int K)
{
    constexpr int BM = 128, BN = 128, BK = 16, PAD = 4;
    __shared__ unsigned As_hi[BK][BM + PAD];
    __shared__ unsigned As_lo[BK][BM + PAD];
    __shared__ unsigned Bs_hi[BK][BN + PAD];
    __shared__ unsigned Bs_lo[BK][BN + PAD];

    const int tid  = threadIdx.x;
    const int warp = tid >> 5, lane = tid & 31;
    const int g = lane >> 2, t = lane & 3;      // octet row, quad col
    const int wm = warp >> 2, wn = warp & 3;    // 2 x 4 warp grid
    const int row0 = blockIdx.y * BM;
    const int col0 = blockIdx.x * BN;

    float acc[4][4][4];
#pragma unroll
    for (int mi = 0; mi < 4; mi++)
#pragma unroll
        for (int ni = 0; ni < 4; ni++)
#pragma unroll
            for (int r = 0; r < 4; r++) acc[mi][ni][r] = 0.f;

    for (int k0 = 0; k0 < K; k0 += BK) {
        // Stage A tile (BM x BK): idx -> k = idx&15, m = idx>>4
#pragma unroll
        for (int i = 0; i < 8; i++) {
            int idx = tid + i * 256;
            int k = idx & 15, m = idx >> 4;
            int gr = row0 + m, gk = k0 + k;
            float v = (gr < M && gk < K) ? A[(size_t)gr * K + gk] : 0.f;
            unsigned hi = f2tf32(v);
            As_hi[k][m] = hi;
            As_lo[k][m] = f2tf32(v - __uint_as_float(hi));
        }
        // Stage B tile (BK x BN): idx -> n = idx&127, k = idx>>7 (coalesced)
#pragma unroll
        for (int i = 0; i < 8; i++) {
            int idx = tid + i * 256;
            int n = idx & 127, k = idx >> 7;
            int gk = k0 + k;
            float v = (gk < K) ? B[(size_t)gk * N + col0 + n] : 0.f;
            unsigned hi = f2tf32(v);
            Bs_hi[k][n] = hi;
            Bs_lo[k][n] = f2tf32(v - __uint_as_float(hi));
        }
        __syncthreads();

#pragma unroll
        for (int ks = 0; ks < BK; ks += 8) {
            // A fragments for this warp's 4 m-frags (rows wm*64 + mi*16)
            unsigned ah[4][4], al[4][4];
#pragma unroll
            for (int mi = 0; mi < 4; mi++) {
                int mr = wm * 64 + mi * 16;
                ah[mi][0] = As_hi[ks + t    ][mr + g    ];
                ah[mi][1] = As_hi[ks + t    ][mr + g + 8];
                ah[mi][2] = As_hi[ks + t + 4][mr + g    ];
                ah[mi][3] = As_hi[ks + t + 4][mr + g + 8];
                al[mi][0] = As_lo[ks + t    ][mr + g    ];
                al[mi][1] = As_lo[ks + t    ][mr + g + 8];
                al[mi][2] = As_lo[ks + t + 4][mr + g    ];
                al[mi][3] = As_lo[ks + t + 4][mr + g + 8];
            }
#pragma unroll
            for (int ni = 0; ni < 4; ni++) {
                int nc = wn * 32 + ni * 8;
                unsigned bh[2], bl[2];
                bh[0] = Bs_hi[ks + t    ][nc + g];
                bh[1] = Bs_hi[ks + t + 4][nc + g];
                bl[0] = Bs_lo[ks + t    ][nc + g];
                bl[1] = Bs_lo[ks + t + 4][nc + g];
#pragma unroll
                for (int mi = 0; mi < 4; mi++) {
                    mma_tf32(acc[mi][ni], ah[mi], bh);  // hi*hi
                    mma_tf32(acc[mi][ni], ah[mi], bl);  // hi*lo
                    mma_tf32(acc[mi][ni], al[mi], bh);  // lo*hi
                }
            }
        }
        __syncthreads();
    }

    // Epilogue: bias + optional ReLU, float2 stores.
#pragma unroll
    for (int mi = 0; mi < 4; mi++) {
        int r0 = row0 + wm * 64 + mi * 16 + g;
        int r1 = r0 + 8;
#pragma unroll
        for (int ni = 0; ni < 4; ni++) {
            int c = col0 + wn * 32 + ni * 8 + 2 * t;
            float b0 = bias[c], b1 = bias[c + 1];
            float2 v0 = make_float2(acc[mi][ni][0] + b0, acc[mi][ni][1] + b1);
            float2 v1 = make_float2(acc[mi][ni][2] + b0, acc[mi][ni][3] + b1);
            if (RELU) {
                v0.x = fmaxf(v0.x, 0.f); v0.y = fmaxf(v0.y, 0.f);
                v1.x = fmaxf(v1.x, 0.f); v1.y = fmaxf(v1.y, 0.f);
            }
            if (r0 < M) *reinterpret_cast<float2*>(&C[(size_t)r0 * N + c]) = v0;
            if (r1 < M) *reinterpret_cast<float2*>(&C[(size_t)r1 * N + c]) = v1;
        }
    }
}

// Stage 1: H = relu(X @ W1 + b1), subject (z=0) / object (z=1)
__global__ void __launch_bounds__(256, 2)
mlp_stage1(const float* __restrict__ X,
           const float* __restrict__ Ws_w1, const float* __restrict__ Ws_b1,
           const float* __restrict__ Wo_w1, const float* __restrict__ Wo_b1)
{
    const float* B    = (blockIdx.z == 0) ? Ws_w1 : Wo_w1;
    const float* bias = (blockIdx.z == 0) ? Ws_b1 : Wo_b1;
    float*       C    = (blockIdx.z == 0) ? g_Hs  : g_Ho;
    gemm_tf32_tile<true>(X, B, bias, C, N_DET, HID_DIM, IN_DIM);
}

// Stage 2: T = H @ W2 + b2 -> subject/object tables
__global__ void __launch_bounds__(256, 2)
mlp_stage2(const float* __restrict__ Ws_w2, const float* __restrict__ Ws_b2,
           const float* __restrict__ Wo_w2, const float* __restrict__ Wo_b2)
{
    const float* A    = (blockIdx.z == 0) ? g_Hs  : g_Ho;
    const float* B    = (blockIdx.z == 0) ? Ws_w2 : Wo_w2;
    const float* bias = (blockIdx.z == 0) ? Ws_b2 : Wo_b2;
    float*       C    = (blockIdx.z == 0) ? g_S   : g_O;
    gemm_tf32_tile<false>(A, B, bias, C, N_DET, OUT_DIM, HID_DIM);
}

// Edge phase: warp per edge. Gather 2x128 floats (float4 per lane), dot,
// warp shfl reduce, sigmoid. Index dtype resolved at runtime via g_idx64.
__global__ void __launch_bounds__(256)
edge_kernel(const void* __restrict__ einds, float* __restrict__ out, int nE)
{
    int w    = (blockIdx.x * blockDim.x + threadIdx.x) >> 5;
    int lane = threadIdx.x & 31;
    if (w >= nE) return;

    long long i1, i2;
    if (g_idx64) {
        const long long* e = (const long long*)einds;
        i1 = __ldg(&e[3LL * w + 1]);
        i2 = __ldg(&e[3LL * w + 2]);
    } else {
        const int* e = (const int*)einds;
        i1 = __ldg(&e[3 * w + 1]);
        i2 = __ldg(&e[3 * w + 2]);
    }

    const float4* s = reinterpret_cast<const float4*>(g_S + i1 * OUT_DIM);
    const float4* o = reinterpret_cast<const float4*>(g_O + i2 * OUT_DIM);
    float4 a = s[lane];
    float4 b = o[lane];
    float sum = a.x * b.x + a.y * b.y + a.z * b.z + a.w * b.w;

#pragma unroll
    for (int off = 16; off; off >>= 1)
        sum += __shfl_xor_sync(0xffffffffu, sum, off);

    if (lane == 0)
        out[w] = 1.f / (1.f + __expf(-sum));
}

extern "C" void kernel_launch(void* const* d_in, const int* in_sizes, int n_in,
                              void* d_out, int out_size)
{
    const float* X     = (const float*)d_in[0];
    const void*  E     = d_in[1];
    const float* Ws_w1 = (const float*)d_in[2];
    const float* Ws_b1 = (const float*)d_in[3];
    const float* Ws_w2 = (const float*)d_in[4];
    const float* Ws_b2 = (const float*)d_in[5];
    const float* Wo_w1 = (const float*)d_in[6];
    const float* Wo_b1 = (const float*)d_in[7];
    const float* Wo_w2 = (const float*)d_in[8];
    const float* Wo_b2 = (const float*)d_in[9];

    probe_dtype<<<1, 1>>>((const long long*)E);

    const int mtiles = (N_DET + 127) / 128;          // 157

    dim3 g1(HID_DIM / 128, mtiles, 2);               // (2, 157, 2)
    mlp_stage1<<<g1, 256>>>(X, Ws_w1, Ws_b1, Wo_w1, Wo_b1);

    dim3 g2(OUT_DIM / 128, mtiles, 2);               // (1, 157, 2)
    mlp_stage2<<<g2, 256>>>(Ws_w2, Ws_b2, Wo_w2, Wo_b2);

    int nE = in_sizes[1] / 3;                        // 1,000,000
    int nThreads = 256;
    long long totalThreads = (long long)nE * 32;
    int nBlocks = (int)((totalThreads + nThreads - 1) / nThreads);
    edge_kernel<<<nBlocks, nThreads>>>(E, (float*)d_out, nE);
}

// round 6
// speedup vs baseline: 1.9755x; 1.4181x over previous
#include <cuda_runtime.h>
#include <cuda_bf16.h>

// Problem constants (from reference)
#define N_DET   20000
#define IN_DIM  151
#define HID_DIM 256
#define OUT_DIM 128

// Scratch: __device__ globals (allocation is forbidden). 16B-aligned.
__device__ __align__(16) float g_Hs[N_DET * HID_DIM];   // relu(X @ Ws_w1 + b1)
__device__ __align__(16) float g_Ho[N_DET * HID_DIM];   // relu(X @ Wo_w1 + b1)
__device__ __align__(16) float g_S [N_DET * OUT_DIM];   // subject table
__device__ __align__(16) float g_O [N_DET * OUT_DIM];   // object table
__device__ int g_idx64;                                  // 1 if edge_inds is int64

// ---------------------------------------------------------------------------
// Probe: decide whether the edge index buffer is int64 or int32.
// ---------------------------------------------------------------------------
__global__ void probe_dtype(const long long* __restrict__ e)
{
    bool ok64 = true;
    for (int i = 0; i < 48; i++) {
        long long v = e[i];
        if (v < 0 || v >= N_DET) ok64 = false;
    }
    g_idx64 = ok64 ? 1 : 0;
}

// ---------------------------------------------------------------------------
// bf16 split helpers: x = hi + lo, each bf16 (8 mantissa bits -> ~16 total).
// ---------------------------------------------------------------------------
__device__ __forceinline__ void split_bf16(float v, unsigned short& hi, unsigned short& lo)
{
    __nv_bfloat16 h = __float2bfloat16(v);
    __nv_bfloat16 l = __float2bfloat16(v - __bfloat162float(h));
    hi = __bfloat16_as_ushort(h);
    lo = __bfloat16_as_ushort(l);
}

__device__ __forceinline__ unsigned pack2(unsigned short a, unsigned short b)
{
    return (unsigned)a | ((unsigned)b << 16);
}

// D += A(16x16,row) * B(16x8,col); bf16 inputs, fp32 accum.
__device__ __forceinline__ void mma_bf16(float* d, const unsigned* a, const unsigned* b)
{
    asm("mma.sync.aligned.m16n8k16.row.col.f32.bf16.bf16.f32 "
        "{%0,%1,%2,%3}, {%4,%5,%6,%7}, {%8,%9}, {%0,%1,%2,%3};"
        : "+f"(d[0]), "+f"(d[1]), "+f"(d[2]), "+f"(d[3])
        : "r"(a[0]), "r"(a[1]), "r"(a[2]), "r"(a[3]), "r"(b[0]), "r"(b[1]));
}

// ---------------------------------------------------------------------------
// bf16x3 GEMM tile: C[M,N] = A[M,K] @ B[K,N] + bias, optional ReLU.
// BM=128, BN=128, BK=16, 256 threads (8 warps as 2x4), warp tile 64x32.
// smem holds k-adjacent PAIRS packed into 32-bit words: one LDS per frag reg.
// ---------------------------------------------------------------------------
template <bool RELU>
__device__ __forceinline__ void gemm_bf16x3_tile(const float* __restrict__ A,
                                                 const float* __restrict__ B,
                                                 const float* __restrict__ bias,
                                                 float* __restrict__ C,
                                                 int M, int N, int K)
{
    constexpr int BM = 128, BN = 128, PAD = 4;
    // [k2][m] where k2 indexes k-pairs (8 pairs = 16 k per tile)
    __shared__ unsigned As_hi[8][BM + PAD];
    __shared__ unsigned As_lo[8][BM + PAD];
    __shared__ unsigned Bs_hi[8][BN + PAD];
    __shared__ unsigned Bs_lo[8][BN + PAD];

    const int tid  = threadIdx.x;
    const int warp = tid >> 5, lane = tid & 31;
    const int g = lane >> 2, t = lane & 3;      // row-in-octet, k-pair quad
    const int wm = warp >> 2, wn = warp & 3;    // 2 x 4 warp grid
    const int row0 = blockIdx.y * BM;
    const int col0 = blockIdx.x * BN;

    float acc[4][4][4];
#pragma unroll
    for (int mi = 0; mi < 4; mi++)
#pragma unroll
        for (int ni = 0; ni < 4; ni++)
#pragma unroll
            for (int r = 0; r < 4; r++) acc[mi][ni][r] = 0.f;

    for (int k0 = 0; k0 < K; k0 += 16) {
        // Stage A tile (BM x 8 pairs): idx -> k2 = idx&7, m = idx>>3
#pragma unroll
        for (int i = 0; i < 4; i++) {
            int idx = tid + i * 256;
            int k2 = idx & 7, m = idx >> 3;
            int gr = row0 + m;
            int gk = k0 + 2 * k2;
            float v0 = 0.f, v1 = 0.f;
            if (gr < M) {
                if (gk     < K) v0 = A[(size_t)gr * K + gk];
                if (gk + 1 < K) v1 = A[(size_t)gr * K + gk + 1];
            }
            unsigned short h0, l0, h1, l1;
            split_bf16(v0, h0, l0);
            split_bf16(v1, h1, l1);
            As_hi[k2][m] = pack2(h0, h1);
            As_lo[k2][m] = pack2(l0, l1);
        }
        // Stage B tile (8 pairs x BN): idx -> n = idx&127, k2 = idx>>7 (coalesced)
#pragma unroll
        for (int i = 0; i < 4; i++) {
            int idx = tid + i * 256;
            int n = idx & 127, k2 = idx >> 7;
            int gk = k0 + 2 * k2;
            float v0 = (gk     < K) ? B[(size_t)gk * N + col0 + n]       : 0.f;
            float v1 = (gk + 1 < K) ? B[(size_t)(gk + 1) * N + col0 + n] : 0.f;
            unsigned short h0, l0, h1, l1;
            split_bf16(v0, h0, l0);
            split_bf16(v1, h1, l1);
            Bs_hi[k2][n] = pack2(h0, h1);
            Bs_lo[k2][n] = pack2(l0, l1);
        }
        __syncthreads();

        // A fragments for this warp's 4 m-frags (one k16 chunk = whole tile)
        unsigned ah[4][4], al[4][4];
#pragma unroll
        for (int mi = 0; mi < 4; mi++) {
            int mr = wm * 64 + mi * 16;
            ah[mi][0] = As_hi[t    ][mr + g    ];
            ah[mi][1] = As_hi[t    ][mr + g + 8];
            ah[mi][2] = As_hi[t + 4][mr + g    ];
            ah[mi][3] = As_hi[t + 4][mr + g + 8];
            al[mi][0] = As_lo[t    ][mr + g    ];
            al[mi][1] = As_lo[t    ][mr + g + 8];
            al[mi][2] = As_lo[t + 4][mr + g    ];
            al[mi][3] = As_lo[t + 4][mr + g + 8];
        }
#pragma unroll
        for (int ni = 0; ni < 4; ni++) {
            int nc = wn * 32 + ni * 8;
            unsigned bh[2], bl[2];
            bh[0] = Bs_hi[t    ][nc + g];
            bh[1] = Bs_hi[t + 4][nc + g];
            bl[0] = Bs_lo[t    ][nc + g];
            bl[1] = Bs_lo[t + 4][nc + g];
#pragma unroll
            for (int mi = 0; mi < 4; mi++) {
                mma_bf16(acc[mi][ni], ah[mi], bh);  // hi*hi
                mma_bf16(acc[mi][ni], ah[mi], bl);  // hi*lo
                mma_bf16(acc[mi][ni], al[mi], bh);  // lo*hi
            }
        }
        __syncthreads();
    }

    // Epilogue: bias + optional ReLU, float2 stores.
#pragma unroll
    for (int mi = 0; mi < 4; mi++) {
        int r0 = row0 + wm * 64 + mi * 16 + g;
        int r1 = r0 + 8;
#pragma unroll
        for (int ni = 0; ni < 4; ni++) {
            int c = col0 + wn * 32 + ni * 8 + 2 * t;
            float b0 = bias[c], b1 = bias[c + 1];
            float2 v0 = make_float2(acc[mi][ni][0] + b0, acc[mi][ni][1] + b1);
            float2 v1 = make_float2(acc[mi][ni][2] + b0, acc[mi][ni][3] + b1);
            if (RELU) {
                v0.x = fmaxf(v0.x, 0.f); v0.y = fmaxf(v0.y, 0.f);
                v1.x = fmaxf(v1.x, 0.f); v1.y = fmaxf(v1.y, 0.f);
            }
            if (r0 < M) *reinterpret_cast<float2*>(&C[(size_t)r0 * N + c]) = v0;
            if (r1 < M) *reinterpret_cast<float2*>(&C[(size_t)r1 * N + c]) = v1;
        }
    }
}

// Stage 1: H = relu(X @ W1 + b1), subject (z=0) / object (z=1)
__global__ void __launch_bounds__(256, 2)
mlp_stage1(const float* __restrict__ X,
           const float* __restrict__ Ws_w1, const float* __restrict__ Ws_b1,
           const float* __restrict__ Wo_w1, const float* __restrict__ Wo_b1)
{
    const float* B    = (blockIdx.z == 0) ? Ws_w1 : Wo_w1;
    const float* bias = (blockIdx.z == 0) ? Ws_b1 : Wo_b1;
    float*       C    = (blockIdx.z == 0) ? g_Hs  : g_Ho;
    gemm_bf16x3_tile<true>(X, B, bias, C, N_DET, HID_DIM, IN_DIM);
}

// Stage 2: T = H @ W2 + b2 -> subject/object tables
__global__ void __launch_bounds__(256, 2)
mlp_stage2(const float* __restrict__ Ws_w2, const float* __restrict__ Ws_b2,
           const float* __restrict__ Wo_w2, const float* __restrict__ Wo_b2)
{
    const float* A    = (blockIdx.z == 0) ? g_Hs  : g_Ho;
    const float* B    = (blockIdx.z == 0) ? Ws_w2 : Wo_w2;
    const float* bias = (blockIdx.z == 0) ? Ws_b2 : Wo_b2;
    float*       C    = (blockIdx.z == 0) ? g_S   : g_O;
    gemm_bf16x3_tile<false>(A, B, bias, C, N_DET, OUT_DIM, HID_DIM);
}

// ---------------------------------------------------------------------------
// Edge phase: 8 lanes per edge (4 edges per warp). Each lane loads 4 float4
// of sbj + 4 of obj (8 independent LDG.128), dots 32 terms, 3-shfl reduce.
// ---------------------------------------------------------------------------
__global__ void __launch_bounds__(256)
edge_kernel(const void* __restrict__ einds, float* __restrict__ out, int nE)
{
    long long warp = (long long)((blockIdx.x * blockDim.x + threadIdx.x) >> 5);
    int lane = threadIdx.x & 31;
    int sub = lane >> 3;          // which of 4 edges in this warp
    int l   = lane & 7;           // lane within edge group
    long long e = warp * 4 + sub;
    if (e >= nE) return;

    long long i1, i2;
    if (g_idx64) {
        const long long* E = (const long long*)einds;
        i1 = __ldg(&E[3 * e + 1]);
        i2 = __ldg(&E[3 * e + 2]);
    } else {
        const int* E = (const int*)einds;
        i1 = __ldg(&E[3 * e + 1]);
        i2 = __ldg(&E[3 * e + 2]);
    }

    const float4* s = reinterpret_cast<const float4*>(g_S + i1 * OUT_DIM);
    const float4* o = reinterpret_cast<const float4*>(g_O + i2 * OUT_DIM);

    float4 a0 = s[l], a1 = s[l + 8], a2 = s[l + 16], a3 = s[l + 24];
    float4 b0 = o[l], b1 = o[l + 8], b2 = o[l + 16], b3 = o[l + 24];

    float sum = a0.x * b0.x + a0.y * b0.y + a0.z * b0.z + a0.w * b0.w
              + a1.x * b1.x + a1.y * b1.y + a1.z * b1.z + a1.w * b1.w
              + a2.x * b2.x + a2.y * b2.y + a2.z * b2.z + a2.w * b2.w
              + a3.x * b3.x + a3.y * b3.y + a3.z * b3.z + a3.w * b3.w;

    sum += __shfl_xor_sync(0xffffffffu, sum, 4);
    sum += __shfl_xor_sync(0xffffffffu, sum, 2);
    sum += __shfl_xor_sync(0xffffffffu, sum, 1);

    if (l == 0)
        out[e] = 1.f / (1.f + __expf(-sum));
}

extern "C" void kernel_launch(void* const* d_in, const int* in_sizes, int n_in,
                              void* d_out, int out_size)
{
    const float* X     = (const float*)d_in[0];
    const void*  E     = d_in[1];
    const float* Ws_w1 = (const float*)d_in[2];
    const float* Ws_b1 = (const float*)d_in[3];
    const float* Ws_w2 = (const float*)d_in[4];
    const float* Ws_b2 = (const float*)d_in[5];
    const float* Wo_w1 = (const float*)d_in[6];
    const float* Wo_b1 = (const float*)d_in[7];
    const float* Wo_w2 = (const float*)d_in[8];
    const float* Wo_b2 = (const float*)d_in[9];

    probe_dtype<<<1, 1>>>((const long long*)E);

    const int mtiles = (N_DET + 127) / 128;          // 157

    dim3 g1(HID_DIM / 128, mtiles, 2);               // (2, 157, 2)
    mlp_stage1<<<g1, 256>>>(X, Ws_w1, Ws_b1, Wo_w1, Wo_b1);

    dim3 g2(OUT_DIM / 128, mtiles, 2);               // (1, 157, 2)
    mlp_stage2<<<g2, 256>>>(Ws_w2, Ws_b2, Wo_w2, Wo_b2);

    int nE = in_sizes[1] / 3;                        // 1,000,000
    long long totalWarps = ((long long)nE + 3) / 4;
    long long totalThreads = totalWarps * 32;
    int nThreads = 256;
    int nBlocks = (int)((totalThreads + nThreads - 1) / nThreads);
    edge_kernel<<<nBlocks, nThreads>>>(E, (float*)d_out, nE);
}

// round 7
// speedup vs baseline: 2.2638x; 1.1460x over previous
#include <cuda_runtime.h>
#include <cuda_bf16.h>

// Problem constants
#define N_DET   20000
#define IN_DIM  151
#define HID_DIM 256
#define OUT_DIM 128
#define IN_P    80       // padded k-pairs for IN_DIM (76 real, 4 zero)
#define HID_P   128      // k-pairs for HID_DIM

// Scratch (allocation forbidden -> __device__ globals)
__device__ __align__(16) float    g_S[N_DET * OUT_DIM];
__device__ __align__(16) float    g_O[N_DET * OUT_DIM];
__device__ __align__(16) unsigned g_Xp_hi[N_DET * IN_P];
__device__ __align__(16) unsigned g_Xp_lo[N_DET * IN_P];
__device__ __align__(16) unsigned g_W1p_hi[2][IN_P * HID_DIM];
__device__ __align__(16) unsigned g_W1p_lo[2][IN_P * HID_DIM];
__device__ __align__(16) unsigned g_W2p_hi[2][HID_P * OUT_DIM];
__device__ __align__(16) unsigned g_W2p_lo[2][HID_P * OUT_DIM];
__device__ int g_idx64;

// ---------------------------------------------------------------------------
__global__ void probe_dtype(const long long* __restrict__ e)
{
    bool ok64 = true;
    for (int i = 0; i < 48; i++) {
        long long v = e[i];
        if (v < 0 || v >= N_DET) ok64 = false;
    }
    g_idx64 = ok64 ? 1 : 0;
}

// ---------------------------------------------------------------------------
// bf16 split helpers
// ---------------------------------------------------------------------------
__device__ __forceinline__ void split_bf16(float v, unsigned short& hi, unsigned short& lo)
{
    __nv_bfloat16 h = __float2bfloat16(v);
    __nv_bfloat16 l = __float2bfloat16(v - __bfloat162float(h));
    hi = __bfloat16_as_ushort(h);
    lo = __bfloat16_as_ushort(l);
}
__device__ __forceinline__ unsigned pack2(unsigned short a, unsigned short b)
{
    return (unsigned)a | ((unsigned)b << 16);
}
__device__ __forceinline__ void split_pair(float v0, float v1, unsigned& hi, unsigned& lo)
{
    unsigned short h0, l0, h1, l1;
    split_bf16(v0, h0, l0);
    split_bf16(v1, h1, l1);
    hi = pack2(h0, h1);
    lo = pack2(l0, l1);
}

// D += A(16x16,row) * B(16x8,col); bf16 inputs, fp32 accum.
__device__ __forceinline__ void mma_bf16(float* d, const unsigned* a, const unsigned* b)
{
    asm("mma.sync.aligned.m16n8k16.row.col.f32.bf16.bf16.f32 "
        "{%0,%1,%2,%3}, {%4,%5,%6,%7}, {%8,%9}, {%0,%1,%2,%3};"
        : "+f"(d[0]), "+f"(d[1]), "+f"(d[2]), "+f"(d[3])
        : "r"(a[0]), "r"(a[1]), "r"(a[2]), "r"(a[3]), "r"(b[0]), "r"(b[1]));
}

// ---------------------------------------------------------------------------
// Prep: split X into packed bf16 k-pairs (padded to IN_P pairs per row).
// ---------------------------------------------------------------------------
__global__ void prep_X(const float* __restrict__ X)
{
    int idx = blockIdx.x * blockDim.x + threadIdx.x;
    if (idx >= N_DET * IN_P) return;
    int row = idx / IN_P, j = idx - row * IN_P;
    float v0 = (2 * j     < IN_DIM) ? X[(size_t)row * IN_DIM + 2 * j]     : 0.f;
    float v1 = (2 * j + 1 < IN_DIM) ? X[(size_t)row * IN_DIM + 2 * j + 1] : 0.f;
    unsigned hi, lo;
    split_pair(v0, v1, hi, lo);
    g_Xp_hi[idx] = hi;
    g_Xp_lo[idx] = lo;
}

// Prep: split both nets' W1 (IN_P x HID_DIM pairs) and W2 (HID_P x OUT_DIM).
__global__ void prep_W(const float* __restrict__ Ws_w1, const float* __restrict__ Wo_w1,
                       const float* __restrict__ Ws_w2, const float* __restrict__ Wo_w2)
{
    int idx = blockIdx.x * blockDim.x + threadIdx.x;
    const int W1TOT = 2 * IN_P * HID_DIM;    // 40960
    const int W2TOT = 2 * HID_P * OUT_DIM;   // 32768
    if (idx < W1TOT) {
        int net = idx / (IN_P * HID_DIM);
        int r = idx - net * (IN_P * HID_DIM);
        int j = r / HID_DIM, n = r - j * HID_DIM;
        const float* W = net ? Wo_w1 : Ws_w1;
        float v0 = (2 * j     < IN_DIM) ? W[(size_t)(2 * j)     * HID_DIM + n] : 0.f;
        float v1 = (2 * j + 1 < IN_DIM) ? W[(size_t)(2 * j + 1) * HID_DIM + n] : 0.f;
        unsigned hi, lo;
        split_pair(v0, v1, hi, lo);
        g_W1p_hi[net][r] = hi;
        g_W1p_lo[net][r] = lo;
    } else if (idx < W1TOT + W2TOT) {
        int k = idx - W1TOT;
        int net = k / (HID_P * OUT_DIM);
        int r = k - net * (HID_P * OUT_DIM);
        int j = r / OUT_DIM, n = r - j * OUT_DIM;
        const float* W = net ? Wo_w2 : Ws_w2;
        float v0 = W[(size_t)(2 * j)     * OUT_DIM + n];
        float v1 = W[(size_t)(2 * j + 1) * OUT_DIM + n];
        unsigned hi, lo;
        split_pair(v0, v1, hi, lo);
        g_W2p_hi[net][r] = hi;
        g_W2p_lo[net][r] = lo;
    }
}

// ---------------------------------------------------------------------------
// Fused MLP: per CTA = 128 rows x one net. Phase 1: H = relu(X@W1+b1)
// (128x256) kept split-packed in smem. Phase 2: T = H@W2+b2 -> g_S/g_O.
// 512 threads = 16 warps (4x4). Phase-1 warp tile 32x64, phase-2 32x32.
// All operands pre-split bf16 pairs; zero conversions in the hot loop.
// ---------------------------------------------------------------------------
#define SMEM_WORDS (HID_P * 132 * 2 + 8 * 132 * 2 + 8 * 260 * 2)

__global__ __launch_bounds__(512, 1)
void fused_mlp(const float* __restrict__ b1s, const float* __restrict__ b1o,
               const float* __restrict__ b2s, const float* __restrict__ b2o)
{
    extern __shared__ unsigned sm[];
    unsigned* Hs_hi = sm;                       // [HID_P][132]
    unsigned* Hs_lo = Hs_hi + HID_P * 132;
    unsigned* SA_hi = Hs_lo + HID_P * 132;      // [8][132]  phase-1 A stage
    unsigned* SA_lo = SA_hi + 8 * 132;
    unsigned* SB_hi = SA_lo + 8 * 132;          // [8][260]  phase-1 B stage (phase-2 reuses w/ stride 132)
    unsigned* SB_lo = SB_hi + 8 * 260;

    const int tid  = threadIdx.x;
    const int warp = tid >> 5, lane = tid & 31;
    const int g = lane >> 2, t = lane & 3;
    const int wm = warp >> 2, wn = warp & 3;    // 4 x 4 warp grid
    const int row0 = blockIdx.x * 128;
    const int net  = blockIdx.y;

    const unsigned* W1h = g_W1p_hi[net];
    const unsigned* W1l = g_W1p_lo[net];
    const unsigned* W2h = g_W2p_hi[net];
    const unsigned* W2l = g_W2p_lo[net];
    const float* b1 = net ? b1o : b1s;
    const float* b2 = net ? b2o : b2s;
    float* out = net ? g_O : g_S;

    // ---------------- Phase 1: H = relu(X @ W1 + b1) ----------------
    float acc[2][8][4];
#pragma unroll
    for (int mi = 0; mi < 2; mi++)
#pragma unroll
        for (int ni = 0; ni < 8; ni++)
#pragma unroll
            for (int r = 0; r < 4; r++) acc[mi][ni][r] = 0.f;

    for (int s = 0; s < IN_P / 8; s++) {        // 10 k-steps of 8 pairs
        // Stage A: [8][128] pairs from g_Xp
#pragma unroll
        for (int i = 0; i < 2; i++) {
            int idx = tid + i * 512;
            int k2 = idx & 7, m = idx >> 3;
            int row = row0 + m;
            unsigned hi = 0, lo = 0;
            if (row < N_DET) {
                int off = row * IN_P + s * 8 + k2;
                hi = g_Xp_hi[off];
                lo = g_Xp_lo[off];
            }
            SA_hi[k2 * 132 + m] = hi;
            SA_lo[k2 * 132 + m] = lo;
        }
        // Stage B: [8][256] pairs from W1p (coalesced)
#pragma unroll
        for (int i = 0; i < 4; i++) {
            int idx = tid + i * 512;
            int n = idx & 255, k2 = idx >> 8;
            int off = (s * 8 + k2) * HID_DIM + n;
            SB_hi[k2 * 260 + n] = W1h[off];
            SB_lo[k2 * 260 + n] = W1l[off];
        }
        __syncthreads();

        unsigned ah[2][4], al[2][4];
#pragma unroll
        for (int mi = 0; mi < 2; mi++) {
            int mr = wm * 32 + mi * 16;
            ah[mi][0] = SA_hi[t * 132 + mr + g];
            ah[mi][1] = SA_hi[t * 132 + mr + g + 8];
            ah[mi][2] = SA_hi[(t + 4) * 132 + mr + g];
            ah[mi][3] = SA_hi[(t + 4) * 132 + mr + g + 8];
            al[mi][0] = SA_lo[t * 132 + mr + g];
            al[mi][1] = SA_lo[t * 132 + mr + g + 8];
            al[mi][2] = SA_lo[(t + 4) * 132 + mr + g];
            al[mi][3] = SA_lo[(t + 4) * 132 + mr + g + 8];
        }
#pragma unroll
        for (int ni = 0; ni < 8; ni++) {
            int nc = wn * 64 + ni * 8;
            unsigned bh[2], bl[2];
            bh[0] = SB_hi[t * 260 + nc + g];
            bh[1] = SB_hi[(t + 4) * 260 + nc + g];
            bl[0] = SB_lo[t * 260 + nc + g];
            bl[1] = SB_lo[(t + 4) * 260 + nc + g];
#pragma unroll
            for (int mi = 0; mi < 2; mi++) {
                mma_bf16(acc[mi][ni], ah[mi], bh);
                mma_bf16(acc[mi][ni], ah[mi], bl);
                mma_bf16(acc[mi][ni], al[mi], bh);
            }
        }
        __syncthreads();
    }

    // H epilogue: bias + relu, split-pack straight into smem [k2][m]
#pragma unroll
    for (int mi = 0; mi < 2; mi++) {
        int r0 = wm * 32 + mi * 16 + g;
        int r1 = r0 + 8;
#pragma unroll
        for (int ni = 0; ni < 8; ni++) {
            int c0 = wn * 64 + ni * 8 + 2 * t;
            float bb0 = __ldg(&b1[c0]), bb1 = __ldg(&b1[c0 + 1]);
            float v00 = fmaxf(acc[mi][ni][0] + bb0, 0.f);
            float v01 = fmaxf(acc[mi][ni][1] + bb1, 0.f);
            float v10 = fmaxf(acc[mi][ni][2] + bb0, 0.f);
            float v11 = fmaxf(acc[mi][ni][3] + bb1, 0.f);
            int k2 = c0 >> 1;                   // = wn*32 + ni*4 + t
            unsigned hi, lo;
            split_pair(v00, v01, hi, lo);
            Hs_hi[k2 * 132 + r0] = hi;
            Hs_lo[k2 * 132 + r0] = lo;
            split_pair(v10, v11, hi, lo);
            Hs_hi[k2 * 132 + r1] = hi;
            Hs_lo[k2 * 132 + r1] = lo;
        }
    }
    __syncthreads();

    // ---------------- Phase 2: T = H @ W2 + b2 ----------------
    float acc2[2][4][4];
#pragma unroll
    for (int mi = 0; mi < 2; mi++)
#pragma unroll
        for (int ni = 0; ni < 4; ni++)
#pragma unroll
            for (int r = 0; r < 4; r++) acc2[mi][ni][r] = 0.f;

    for (int s = 0; s < HID_P / 8; s++) {       // 16 k-steps
        // Stage B2: [8][128] pairs from W2p (reuse SB region, stride 132)
#pragma unroll
        for (int i = 0; i < 2; i++) {
            int idx = tid + i * 512;
            int n = idx & 127, k2 = idx >> 7;
            int off = (s * 8 + k2) * OUT_DIM + n;
            SB_hi[k2 * 132 + n] = W2h[off];
            SB_lo[k2 * 132 + n] = W2l[off];
        }
        __syncthreads();

        unsigned ah[2][4], al[2][4];
#pragma unroll
        for (int mi = 0; mi < 2; mi++) {
            int mr = wm * 32 + mi * 16;
            int kb = s * 8;
            ah[mi][0] = Hs_hi[(kb + t) * 132 + mr + g];
            ah[mi][1] = Hs_hi[(kb + t) * 132 + mr + g + 8];
            ah[mi][2] = Hs_hi[(kb + t + 4) * 132 + mr + g];
            ah[mi][3] = Hs_hi[(kb + t + 4) * 132 + mr + g + 8];
            al[mi][0] = Hs_lo[(kb + t) * 132 + mr + g];
            al[mi][1] = Hs_lo[(kb + t) * 132 + mr + g + 8];
            al[mi][2] = Hs_lo[(kb + t + 4) * 132 + mr + g];
            al[mi][3] = Hs_lo[(kb + t + 4) * 132 + mr + g + 8];
        }
#pragma unroll
        for (int ni = 0; ni < 4; ni++) {
            int nc = wn * 32 + ni * 8;
            unsigned bh[2], bl[2];
            bh[0] = SB_hi[t * 132 + nc + g];
            bh[1] = SB_hi[(t + 4) * 132 + nc + g];
            bl[0] = SB_lo[t * 132 + nc + g];
            bl[1] = SB_lo[(t + 4) * 132 + nc + g];
#pragma unroll
            for (int mi = 0; mi < 2; mi++) {
                mma_bf16(acc2[mi][ni], ah[mi], bh);
                mma_bf16(acc2[mi][ni], ah[mi], bl);
                mma_bf16(acc2[mi][ni], al[mi], bh);
            }
        }
        __syncthreads();
    }

    // Output epilogue
#pragma unroll
    for (int mi = 0; mi < 2; mi++) {
        int r0 = row0 + wm * 32 + mi * 16 + g;
        int r1 = r0 + 8;
#pragma unroll
        for (int ni = 0; ni < 4; ni++) {
            int c = wn * 32 + ni * 8 + 2 * t;
            float bb0 = __ldg(&b2[c]), bb1 = __ldg(&b2[c + 1]);
            float2 v0 = make_float2(acc2[mi][ni][0] + bb0, acc2[mi][ni][1] + bb1);
            float2 v1 = make_float2(acc2[mi][ni][2] + bb0, acc2[mi][ni][3] + bb1);
            if (r0 < N_DET) *reinterpret_cast<float2*>(&out[(size_t)r0 * OUT_DIM + c]) = v0;
            if (r1 < N_DET) *reinterpret_cast<float2*>(&out[(size_t)r1 * OUT_DIM + c]) = v1;
        }
    }
}

// ---------------------------------------------------------------------------
// Edge phase: 8 lanes per edge (4 edges per warp).
// ---------------------------------------------------------------------------
__global__ void __launch_bounds__(256)
edge_kernel(const void* __restrict__ einds, float* __restrict__ out, int nE)
{
    long long warp = (long long)((blockIdx.x * blockDim.x + threadIdx.x) >> 5);
    int lane = threadIdx.x & 31;
    int sub = lane >> 3;
    int l   = lane & 7;
    long long e = warp * 4 + sub;
    if (e >= nE) return;

    long long i1, i2;
    if (g_idx64) {
        const long long* E = (const long long*)einds;
        i1 = __ldg(&E[3 * e + 1]);
        i2 = __ldg(&E[3 * e + 2]);
    } else {
        const int* E = (const int*)einds;
        i1 = __ldg(&E[3 * e + 1]);
        i2 = __ldg(&E[3 * e + 2]);
    }

    const float4* s = reinterpret_cast<const float4*>(g_S + i1 * OUT_DIM);
    const float4* o = reinterpret_cast<const float4*>(g_O + i2 * OUT_DIM);

    float4 a0 = s[l], a1 = s[l + 8], a2 = s[l + 16], a3 = s[l + 24];
    float4 b0 = o[l], b1 = o[l + 8], b2 = o[l + 16], b3 = o[l + 24];

    float sum = a0.x * b0.x + a0.y * b0.y + a0.z * b0.z + a0.w * b0.w
              + a1.x * b1.x + a1.y * b1.y + a1.z * b1.z + a1.w * b1.w
              + a2.x * b2.x + a2.y * b2.y + a2.z * b2.z + a2.w * b2.w
              + a3.x * b3.x + a3.y * b3.y + a3.z * b3.z + a3.w * b3.w;

    sum += __shfl_xor_sync(0xffffffffu, sum, 4);
    sum += __shfl_xor_sync(0xffffffffu, sum, 2);
    sum += __shfl_xor_sync(0xffffffffu, sum, 1);

    if (l == 0)
        out[e] = 1.f / (1.f + __expf(-sum));
}

extern "C" void kernel_launch(void* const* d_in, const int* in_sizes, int n_in,
                              void* d_out, int out_size)
{
    const float* X     = (const float*)d_in[0];
    const void*  E     = d_in[1];
    const float* Ws_w1 = (const float*)d_in[2];
    const float* Ws_b1 = (const float*)d_in[3];
    const float* Ws_w2 = (const float*)d_in[4];
    const float* Ws_b2 = (const float*)d_in[5];
    const float* Wo_w1 = (const float*)d_in[6];
    const float* Wo_b1 = (const float*)d_in[7];
    const float* Wo_w2 = (const float*)d_in[8];
    const float* Wo_b2 = (const float*)d_in[9];

    static bool attr_set = false;  // idempotent attribute; set before first use
    cudaFuncSetAttribute(fused_mlp, cudaFuncAttributeMaxDynamicSharedMemorySize,
                         SMEM_WORDS * 4);
    (void)attr_set;

    probe_dtype<<<1, 1>>>((const long long*)E);

    int nx = N_DET * IN_P;
    prep_X<<<(nx + 255) / 256, 256>>>(X);
    int nw = 2 * IN_P * HID_DIM + 2 * HID_P * OUT_DIM;
    prep_W<<<(nw + 255) / 256, 256>>>(Ws_w1, Wo_w1, Ws_w2, Wo_w2);

    dim3 gf((N_DET + 127) / 128, 2);             // (157, 2)
    fused_mlp<<<gf, 512, SMEM_WORDS * 4>>>(Ws_b1, Wo_b1, Ws_b2, Wo_b2);

    int nE = in_sizes[1] / 3;                    // 1,000,000
    long long totalWarps = ((long long)nE + 3) / 4;
    long long totalThreads = totalWarps * 32;
    int nThreads = 256;
    int nBlocks = (int)((totalThreads + nThreads - 1) / nThreads);
    edge_kernel<<<nBlocks, nThreads>>>(E, (float*)d_out, nE);
}

// round 8
// speedup vs baseline: 2.6942x; 1.1901x over previous
#include <cuda_runtime.h>
#include <cuda_bf16.h>

// Problem constants
#define N_DET   20000
#define IN_DIM  151
#define HID_DIM 256
#define OUT_DIM 128
#define IN_P    80       // padded k-pairs for IN_DIM (76 real, 4 zero) -> 5 steps of 16
#define HID_P   128      // k-pairs for HID_DIM -> 8 steps of 16

// Scratch (allocation forbidden -> __device__ globals)
__device__ __align__(16) float    g_S[N_DET * OUT_DIM];
__device__ __align__(16) float    g_O[N_DET * OUT_DIM];
__device__ __align__(16) unsigned g_Xp_hi[N_DET * IN_P];
__device__ __align__(16) unsigned g_Xp_lo[N_DET * IN_P];
__device__ __align__(16) unsigned g_W1p_hi[2][IN_P * HID_DIM];
__device__ __align__(16) unsigned g_W1p_lo[2][IN_P * HID_DIM];
__device__ __align__(16) unsigned g_W2p_hi[2][HID_P * OUT_DIM];
__device__ __align__(16) unsigned g_W2p_lo[2][HID_P * OUT_DIM];
__device__ int g_idx64;

// ---------------------------------------------------------------------------
__global__ void probe_dtype(const long long* __restrict__ e)
{
    bool ok64 = true;
    for (int i = 0; i < 48; i++) {
        long long v = e[i];
        if (v < 0 || v >= N_DET) ok64 = false;
    }
    g_idx64 = ok64 ? 1 : 0;
}

// ---------------------------------------------------------------------------
// bf16 split helpers
// ---------------------------------------------------------------------------
__device__ __forceinline__ void split_bf16(float v, unsigned short& hi, unsigned short& lo)
{
    __nv_bfloat16 h = __float2bfloat16(v);
    __nv_bfloat16 l = __float2bfloat16(v - __bfloat162float(h));
    hi = __bfloat16_as_ushort(h);
    lo = __bfloat16_as_ushort(l);
}
__device__ __forceinline__ unsigned pack2(unsigned short a, unsigned short b)
{
    return (unsigned)a | ((unsigned)b << 16);
}
__device__ __forceinline__ void split_pair(float v0, float v1, unsigned& hi, unsigned& lo)
{
    unsigned short h0, l0, h1, l1;
    split_bf16(v0, h0, l0);
    split_bf16(v1, h1, l1);
    hi = pack2(h0, h1);
    lo = pack2(l0, l1);
}

// D += A(16x16,row) * B(16x8,col); bf16 inputs, fp32 accum.
__device__ __forceinline__ void mma_bf16(float* d, const unsigned* a, const unsigned* b)
{
    asm("mma.sync.aligned.m16n8k16.row.col.f32.bf16.bf16.f32 "
        "{%0,%1,%2,%3}, {%4,%5,%6,%7}, {%8,%9}, {%0,%1,%2,%3};"
        : "+f"(d[0]), "+f"(d[1]), "+f"(d[2]), "+f"(d[3])
        : "r"(a[0]), "r"(a[1]), "r"(a[2]), "r"(a[3]), "r"(b[0]), "r"(b[1]));
}

// cp.async 16B global->shared
__device__ __forceinline__ void cp16(unsigned* dst, const unsigned* src)
{
    unsigned d = (unsigned)__cvta_generic_to_shared(dst);
    asm volatile("cp.async.cg.shared.global [%0], [%1], 16;" :: "r"(d), "l"(src));
}
__device__ __forceinline__ void cp_wait_all()
{
    asm volatile("cp.async.wait_all;" ::: "memory");
}

// ---------------------------------------------------------------------------
// Prep: split X into packed bf16 k-pairs (padded to IN_P pairs per row).
// ---------------------------------------------------------------------------
__global__ void prep_X(const float* __restrict__ X)
{
    int idx = blockIdx.x * blockDim.x + threadIdx.x;
    if (idx >= N_DET * IN_P) return;
    int row = idx / IN_P, j = idx - row * IN_P;
    float v0 = (2 * j     < IN_DIM) ? X[(size_t)row * IN_DIM + 2 * j]     : 0.f;
    float v1 = (2 * j + 1 < IN_DIM) ? X[(size_t)row * IN_DIM + 2 * j + 1] : 0.f;
    unsigned hi, lo;
    split_pair(v0, v1, hi, lo);
    g_Xp_hi[idx] = hi;
    g_Xp_lo[idx] = lo;
}

// Prep: split both nets' W1 (IN_P x HID_DIM pairs) and W2 (HID_P x OUT_DIM).
__global__ void prep_W(const float* __restrict__ Ws_w1, const float* __restrict__ Wo_w1,
                       const float* __restrict__ Ws_w2, const float* __restrict__ Wo_w2)
{
    int idx = blockIdx.x * blockDim.x + threadIdx.x;
    const int W1TOT = 2 * IN_P * HID_DIM;    // 40960
    const int W2TOT = 2 * HID_P * OUT_DIM;   // 32768
    if (idx < W1TOT) {
        int net = idx / (IN_P * HID_DIM);
        int r = idx - net * (IN_P * HID_DIM);
        int j = r / HID_DIM, n = r - j * HID_DIM;
        const float* W = net ? Wo_w1 : Ws_w1;
        float v0 = (2 * j     < IN_DIM) ? W[(size_t)(2 * j)     * HID_DIM + n] : 0.f;
        float v1 = (2 * j + 1 < IN_DIM) ? W[(size_t)(2 * j + 1) * HID_DIM + n] : 0.f;
        unsigned hi, lo;
        split_pair(v0, v1, hi, lo);
        g_W1p_hi[net][r] = hi;
        g_W1p_lo[net][r] = lo;
    } else if (idx < W1TOT + W2TOT) {
        int k = idx - W1TOT;
        int net = k / (HID_P * OUT_DIM);
        int r = k - net * (HID_P * OUT_DIM);
        int j = r / OUT_DIM, n = r - j * OUT_DIM;
        const float* W = net ? Wo_w2 : Ws_w2;
        float v0 = W[(size_t)(2 * j)     * OUT_DIM + n];
        float v1 = W[(size_t)(2 * j + 1) * OUT_DIM + n];
        unsigned hi, lo;
        split_pair(v0, v1, hi, lo);
        g_W2p_hi[net][r] = hi;
        g_W2p_lo[net][r] = lo;
    }
}

// ---------------------------------------------------------------------------
// Fused MLP v2: per CTA = 64 rows x one net. 256 threads (8 warps, 2x4).
// Phase 1: H = relu(X@W1+b1) (64x256) kept split-packed in smem.
// Phase 2: T = H@W2+b2 -> g_S/g_O.
// 111.1 KB smem -> 2 CTAs/SM; stages via cp.async; 16 k-pairs per barrier.
// ---------------------------------------------------------------------------
// smem word layout
#define HS_STRIDE 66
#define SA_STRIDE 20
#define SB1_STRIDE 260
#define SB2_STRIDE 132
#define HS_WORDS  (HID_P * HS_STRIDE)        // 8448 per half
#define SA_WORDS  (64 * SA_STRIDE)           // 1280 per half
#define SB_WORDS  (16 * SB1_STRIDE)          // 4160 per half
#define SMEM_WORDS (2 * HS_WORDS + 2 * SA_WORDS + 2 * SB_WORDS)   // 27776 = 111104 B

__global__ __launch_bounds__(256, 2)
void fused_mlp(const float* __restrict__ b1s, const float* __restrict__ b1o,
               const float* __restrict__ b2s, const float* __restrict__ b2o)
{
    extern __shared__ unsigned sm[];
    unsigned* Hs_hi = sm;                    // [HID_P][66]   (k-pair major)
    unsigned* Hs_lo = Hs_hi + HS_WORDS;
    unsigned* SA_hi = Hs_lo + HS_WORDS;      // [64][20]      (row major, 16 pairs + pad)
    unsigned* SA_lo = SA_hi + SA_WORDS;
    unsigned* SB_hi = SA_lo + SA_WORDS;      // [16][260] p1 / [16][132] p2
    unsigned* SB_lo = SB_hi + SB_WORDS;

    const int tid  = threadIdx.x;
    const int warp = tid >> 5, lane = tid & 31;
    const int g = lane >> 2, t = lane & 3;
    const int wm = warp >> 2, wn = warp & 3;   // 2 x 4 warp grid
    const int row0 = blockIdx.x * 64;
    const int net  = blockIdx.y;

    const unsigned* W1h = g_W1p_hi[net];
    const unsigned* W1l = g_W1p_lo[net];
    const unsigned* W2h = g_W2p_hi[net];
    const unsigned* W2l = g_W2p_lo[net];
    const float* b1 = net ? b1o : b1s;
    const float* b2 = net ? b2o : b2s;
    float* out = net ? g_O : g_S;

    // ---------------- Phase 1: H = relu(X @ W1 + b1) ----------------
    float acc[2][8][4];
#pragma unroll
    for (int mi = 0; mi < 2; mi++)
#pragma unroll
        for (int ni = 0; ni < 8; ni++)
#pragma unroll
            for (int r = 0; r < 4; r++) acc[mi][ni][r] = 0.f;

    for (int s = 0; s < IN_P / 16; s++) {      // 5 steps of 16 pairs
        // SA stage: 64 rows x 16 pairs; one 16B chunk per thread per half
        {
            int row = tid >> 2, c = tid & 3;
            int grow = row0 + row;
            if (grow >= N_DET) grow = 0;       // clamp: junk rows discarded in epilogue
            size_t off = (size_t)grow * IN_P + s * 16 + c * 4;
            cp16(&SA_hi[row * SA_STRIDE + c * 4], &g_Xp_hi[off]);
            cp16(&SA_lo[row * SA_STRIDE + c * 4], &g_Xp_lo[off]);
        }
        // SB stage: 16 k2-rows x 256 n; 4 chunks per thread per half
#pragma unroll
        for (int i = 0; i < 4; i++) {
            int idx = tid + i * 256;
            int k2 = idx >> 6, c = idx & 63;
            size_t off = (size_t)(s * 16 + k2) * HID_DIM + c * 4;
            cp16(&SB_hi[k2 * SB1_STRIDE + c * 4], &W1h[off]);
            cp16(&SB_lo[k2 * SB1_STRIDE + c * 4], &W1l[off]);
        }
        cp_wait_all();
        __syncthreads();

#pragma unroll
        for (int kk = 0; kk < 2; kk++) {
            int ko = kk * 8;
            unsigned ah[2][4], al[2][4];
#pragma unroll
            for (int mi = 0; mi < 2; mi++) {
                int mr = wm * 32 + mi * 16;
                ah[mi][0] = SA_hi[(mr + g)     * SA_STRIDE + ko + t];
                ah[mi][1] = SA_hi[(mr + g + 8) * SA_STRIDE + ko + t];
                ah[mi][2] = SA_hi[(mr + g)     * SA_STRIDE + ko + t + 4];
                ah[mi][3] = SA_hi[(mr + g + 8) * SA_STRIDE + ko + t + 4];
                al[mi][0] = SA_lo[(mr + g)     * SA_STRIDE + ko + t];
                al[mi][1] = SA_lo[(mr + g + 8) * SA_STRIDE + ko + t];
                al[mi][2] = SA_lo[(mr + g)     * SA_STRIDE + ko + t + 4];
                al[mi][3] = SA_lo[(mr + g + 8) * SA_STRIDE + ko + t + 4];
            }
#pragma unroll
            for (int ni = 0; ni < 8; ni++) {
                int nc = wn * 64 + ni * 8;
                unsigned bh[2], bl[2];
                bh[0] = SB_hi[(ko + t)     * SB1_STRIDE + nc + g];
                bh[1] = SB_hi[(ko + t + 4) * SB1_STRIDE + nc + g];
                bl[0] = SB_lo[(ko + t)     * SB1_STRIDE + nc + g];
                bl[1] = SB_lo[(ko + t + 4) * SB1_STRIDE + nc + g];
#pragma unroll
                for (int mi = 0; mi < 2; mi++) {
                    mma_bf16(acc[mi][ni], ah[mi], bh);
                    mma_bf16(acc[mi][ni], ah[mi], bl);
                    mma_bf16(acc[mi][ni], al[mi], bh);
                }
            }
        }
        __syncthreads();
    }

    // H epilogue: bias + relu, split-pack into Hs [k2][m]
#pragma unroll
    for (int mi = 0; mi < 2; mi++) {
        int r0 = wm * 32 + mi * 16 + g;
        int r1 = r0 + 8;
#pragma unroll
        for (int ni = 0; ni < 8; ni++) {
            int c0 = wn * 64 + ni * 8 + 2 * t;
            float bb0 = __ldg(&b1[c0]), bb1 = __ldg(&b1[c0 + 1]);
            float v00 = fmaxf(acc[mi][ni][0] + bb0, 0.f);
            float v01 = fmaxf(acc[mi][ni][1] + bb1, 0.f);
            float v10 = fmaxf(acc[mi][ni][2] + bb0, 0.f);
            float v11 = fmaxf(acc[mi][ni][3] + bb1, 0.f);
            int k2 = c0 >> 1;
            unsigned hi, lo;
            split_pair(v00, v01, hi, lo);
            Hs_hi[k2 * HS_STRIDE + r0] = hi;
            Hs_lo[k2 * HS_STRIDE + r0] = lo;
            split_pair(v10, v11, hi, lo);
            Hs_hi[k2 * HS_STRIDE + r1] = hi;
            Hs_lo[k2 * HS_STRIDE + r1] = lo;
        }
    }
    __syncthreads();

    // ---------------- Phase 2: T = H @ W2 + b2 ----------------
    float acc2[2][4][4];
#pragma unroll
    for (int mi = 0; mi < 2; mi++)
#pragma unroll
        for (int ni = 0; ni < 4; ni++)
#pragma unroll
            for (int r = 0; r < 4; r++) acc2[mi][ni][r] = 0.f;

    for (int s = 0; s < HID_P / 16; s++) {     // 8 steps of 16 pairs
        // B2 stage: 16 k2-rows x 128 n; 2 chunks per thread per half
#pragma unroll
        for (int i = 0; i < 2; i++) {
            int idx = tid + i * 256;
            int k2 = idx >> 5, c = idx & 31;
            size_t off = (size_t)(s * 16 + k2) * OUT_DIM + c * 4;
            cp16(&SB_hi[k2 * SB2_STRIDE + c * 4], &W2h[off]);
            cp16(&SB_lo[k2 * SB2_STRIDE + c * 4], &W2l[off]);
        }
        cp_wait_all();
        __syncthreads();

#pragma unroll
        for (int kk = 0; kk < 2; kk++) {
            int ko = kk * 8;
            int kb = s * 16 + ko;
            unsigned ah[2][4], al[2][4];
#pragma unroll
            for (int mi = 0; mi < 2; mi++) {
                int mr = wm * 32 + mi * 16;
                ah[mi][0] = Hs_hi[(kb + t)     * HS_STRIDE + mr + g];
                ah[mi][1] = Hs_hi[(kb + t)     * HS_STRIDE + mr + g + 8];
                ah[mi][2] = Hs_hi[(kb + t + 4) * HS_STRIDE + mr + g];
                ah[mi][3] = Hs_hi[(kb + t + 4) * HS_STRIDE + mr + g + 8];
                al[mi][0] = Hs_lo[(kb + t)     * HS_STRIDE + mr + g];
                al[mi][1] = Hs_lo[(kb + t)     * HS_STRIDE + mr + g + 8];
                al[mi][2] = Hs_lo[(kb + t + 4) * HS_STRIDE + mr + g];
                al[mi][3] = Hs_lo[(kb + t + 4) * HS_STRIDE + mr + g + 8];
            }
#pragma unroll
            for (int ni = 0; ni < 4; ni++) {
                int nc = wn * 32 + ni * 8;
                unsigned bh[2], bl[2];
                bh[0] = SB_hi[(ko + t)     * SB2_STRIDE + nc + g];
                bh[1] = SB_hi[(ko + t + 4) * SB2_STRIDE + nc + g];
                bl[0] = SB_lo[(ko + t)     * SB2_STRIDE + nc + g];
                bl[1] = SB_lo[(ko + t + 4) * SB2_STRIDE + nc + g];
#pragma unroll
                for (int mi = 0; mi < 2; mi++) {
                    mma_bf16(acc2[mi][ni], ah[mi], bh);
                    mma_bf16(acc2[mi][ni], ah[mi], bl);
                    mma_bf16(acc2[mi][ni], al[mi], bh);
                }
            }
        }
        __syncthreads();
    }

    // Output epilogue
#pragma unroll
    for (int mi = 0; mi < 2; mi++) {
        int r0 = row0 + wm * 32 + mi * 16 + g;
        int r1 = r0 + 8;
#pragma unroll
        for (int ni = 0; ni < 4; ni++) {
            int c = wn * 32 + ni * 8 + 2 * t;
            float bb0 = __ldg(&b2[c]), bb1 = __ldg(&b2[c + 1]);
            float2 v0 = make_float2(acc2[mi][ni][0] + bb0, acc2[mi][ni][1] + bb1);
            float2 v1 = make_float2(acc2[mi][ni][2] + bb0, acc2[mi][ni][3] + bb1);
            if (r0 < N_DET) *reinterpret_cast<float2*>(&out[(size_t)r0 * OUT_DIM + c]) = v0;
            if (r1 < N_DET) *reinterpret_cast<float2*>(&out[(size_t)r1 * OUT_DIM + c]) = v1;
        }
    }
}

// ---------------------------------------------------------------------------
// Edge phase: 8 lanes per edge (4 edges per warp).
// ---------------------------------------------------------------------------
__global__ void __launch_bounds__(256)
edge_kernel(const void* __restrict__ einds, float* __restrict__ out, int nE)
{
    long long warp = (long long)((blockIdx.x * blockDim.x + threadIdx.x) >> 5);
    int lane = threadIdx.x & 31;
    int sub = lane >> 3;
    int l   = lane & 7;
    long long e = warp * 4 + sub;
    if (e >= nE) return;

    long long i1, i2;
    if (g_idx64) {
        const long long* E = (const long long*)einds;
        i1 = __ldg(&E[3 * e + 1]);
        i2 = __ldg(&E[3 * e + 2]);
    } else {
        const int* E = (const int*)einds;
        i1 = __ldg(&E[3 * e + 1]);
        i2 = __ldg(&E[3 * e + 2]);
    }

    const float4* s = reinterpret_cast<const float4*>(g_S + i1 * OUT_DIM);
    const float4* o = reinterpret_cast<const float4*>(g_O + i2 * OUT_DIM);

    float4 a0 = s[l], a1 = s[l + 8], a2 = s[l + 16], a3 = s[l + 24];
    float4 b0 = o[l], b1 = o[l + 8], b2 = o[l + 16], b3 = o[l + 24];

    float sum = a0.x * b0.x + a0.y * b0.y + a0.z * b0.z + a0.w * b0.w
              + a1.x * b1.x + a1.y * b1.y + a1.z * b1.z + a1.w * b1.w
              + a2.x * b2.x + a2.y * b2.y + a2.z * b2.z + a2.w * b2.w
              + a3.x * b3.x + a3.y * b3.y + a3.z * b3.z + a3.w * b3.w;

    sum += __shfl_xor_sync(0xffffffffu, sum, 4);
    sum += __shfl_xor_sync(0xffffffffu, sum, 2);
    sum += __shfl_xor_sync(0xffffffffu, sum, 1);

    if (l == 0)
        out[e] = 1.f / (1.f + __expf(-sum));
}

extern "C" void kernel_launch(void* const* d_in, const int* in_sizes, int n_in,
                              void* d_out, int out_size)
{
    const float* X     = (const float*)d_in[0];
    const void*  E     = d_in[1];
    const float* Ws_w1 = (const float*)d_in[2];
    const float* Ws_b1 = (const float*)d_in[3];
    const float* Ws_w2 = (const float*)d_in[4];
    const float* Ws_b2 = (const float*)d_in[5];
    const float* Wo_w1 = (const float*)d_in[6];
    const float* Wo_b1 = (const float*)d_in[7];
    const float* Wo_w2 = (const float*)d_in[8];
    const float* Wo_b2 = (const float*)d_in[9];

    cudaFuncSetAttribute(fused_mlp, cudaFuncAttributeMaxDynamicSharedMemorySize,
                         SMEM_WORDS * 4);

    probe_dtype<<<1, 1>>>((const long long*)E);

    int nx = N_DET * IN_P;
    prep_X<<<(nx + 255) / 256, 256>>>(X);
    int nw = 2 * IN_P * HID_DIM + 2 * HID_P * OUT_DIM;
    prep_W<<<(nw + 255) / 256, 256>>>(Ws_w1, Wo_w1, Ws_w2, Wo_w2);

    dim3 gf((N_DET + 63) / 64, 2);               // (313, 2)
    fused_mlp<<<gf, 256, SMEM_WORDS * 4>>>(Ws_b1, Wo_b1, Ws_b2, Wo_b2);

    int nE = in_sizes[1] / 3;                    // 1,000,000
    long long totalWarps = ((long long)nE + 3) / 4;
    long long totalThreads = totalWarps * 32;
    int nThreads = 256;
    int nBlocks = (int)((totalThreads + nThreads - 1) / nThreads);
    edge_kernel<<<nBlocks, nThreads>>>(E, (float*)d_out, nE);
}